// round 1
// baseline (speedup 1.0000x reference)
#include <cuda_runtime.h>

// ---------------- problem constants ----------------
#define B_  32
#define T_  12
#define BT  (B_*T_)        // 384
#define NNODE 325
#define DD  128
#define FF  128
#define MT  (BT*NNODE)     // 124800

// ---------------- scratch (device globals; no allocation allowed) -------
__device__ float g_xn     [(size_t)MT*128];
__device__ float g_qkv    [(size_t)MT*384];
__device__ float g_coords [(size_t)MT*2];
__device__ float g_h      [(size_t)MT*256];
__device__ float g_w      [(size_t)BT*NNODE*NNODE];
__device__ float g_attnout[(size_t)MT*128];
__device__ float g_gateres[(size_t)MT*128];
__device__ float g_vn     [(size_t)MT*128];
__device__ float g_sg     [(size_t)MT*128];

// ---------------- LayerNorm (warp per row, D=128) + optional coords -----
__global__ __launch_bounds__(256)
void ln_kernel(const float* __restrict__ in, int istride,
               float* __restrict__ out,
               const float* __restrict__ gam, const float* __restrict__ bet,
               int nrows,
               float* __restrict__ coords,
               const float* __restrict__ Wl, const float* __restrict__ bl)
{
    int row = blockIdx.x * 8 + (threadIdx.x >> 5);
    if (row >= nrows) return;
    int lane = threadIdx.x & 31;
    float4 v = *(const float4*)(in + (size_t)row * istride + lane * 4);
    float s  = v.x + v.y + v.z + v.w;
    float ss = v.x*v.x + v.y*v.y + v.z*v.z + v.w*v.w;
#pragma unroll
    for (int o = 16; o > 0; o >>= 1) {
        s  += __shfl_xor_sync(0xffffffffu, s,  o);
        ss += __shfl_xor_sync(0xffffffffu, ss, o);
    }
    float mean = s * (1.f/128.f);
    float var  = ss * (1.f/128.f) - mean * mean;
    float r = rsqrtf(var + 1e-5f);
    int c = lane * 4;
    float o0 = (v.x - mean) * r * gam[c+0] + bet[c+0];
    float o1 = (v.y - mean) * r * gam[c+1] + bet[c+1];
    float o2 = (v.z - mean) * r * gam[c+2] + bet[c+2];
    float o3 = (v.w - mean) * r * gam[c+3] + bet[c+3];
    *(float4*)(out + (size_t)row * 128 + c) = make_float4(o0, o1, o2, o3);
    if (coords) {
        float c0 = o0*Wl[(c+0)*2] + o1*Wl[(c+1)*2] + o2*Wl[(c+2)*2] + o3*Wl[(c+3)*2];
        float c1 = o0*Wl[(c+0)*2+1] + o1*Wl[(c+1)*2+1] + o2*Wl[(c+2)*2+1] + o3*Wl[(c+3)*2+1];
#pragma unroll
        for (int o = 16; o > 0; o >>= 1) {
            c0 += __shfl_xor_sync(0xffffffffu, c0, o);
            c1 += __shfl_xor_sync(0xffffffffu, c1, o);
        }
        if (lane == 0) {
            coords[(size_t)row*2 + 0] = c0 + bl[0];
            coords[(size_t)row*2 + 1] = c1 + bl[1];
        }
    }
}

// ---------------- softmax over rows of length 325 (warp per row) --------
__global__ __launch_bounds__(256)
void softmax_kernel(float* __restrict__ w, int nrows)
{
    int row = blockIdx.x * 8 + (threadIdx.x >> 5);
    if (row >= nrows) return;
    int lane = threadIdx.x & 31;
    float* p = w + (size_t)row * NNODE;
    float v[11];
    float mx = -1e30f;
#pragma unroll
    for (int i = 0; i < 11; i++) {
        int idx = lane + 32 * i;
        v[i] = (idx < NNODE) ? p[idx] : -1e30f;
        mx = fmaxf(mx, v[i]);
    }
#pragma unroll
    for (int o = 16; o > 0; o >>= 1)
        mx = fmaxf(mx, __shfl_xor_sync(0xffffffffu, mx, o));
    float s = 0.f;
#pragma unroll
    for (int i = 0; i < 11; i++) { v[i] = __expf(v[i] - mx); s += v[i]; }
#pragma unroll
    for (int o = 16; o > 0; o >>= 1)
        s += __shfl_xor_sync(0xffffffffu, s, o);
    float inv = 1.f / s;
#pragma unroll
    for (int i = 0; i < 11; i++) {
        int idx = lane + 32 * i;
        if (idx < NNODE) p[idx] = v[i] * inv;
    }
}

// ---------------- generic batched SGEMM, 64x64 tile, BK=8 ---------------
// EPI: 0 = +bias ; 1 = +bias + coords-affine + ReLU ; 2 = +bias, ReLU, +residual
template<bool TRANSB, int EPI>
__global__ __launch_bounds__(256)
void sgemm_kernel(const float* __restrict__ A, int lda, long long sA,
                  const float* __restrict__ Bm, int ldb, long long sB,
                  float* __restrict__ C, int ldc, long long sC,
                  int M, int N, int K,
                  const float* __restrict__ bias,
                  const float* __restrict__ e0,
                  const float* __restrict__ e1,
                  const float* __restrict__ e2)
{
    A  += (long long)blockIdx.z * sA;
    Bm += (long long)blockIdx.z * sB;
    C  += (long long)blockIdx.z * sC;
    int row0 = blockIdx.y * 64;
    int col0 = blockIdx.x * 64;
    __shared__ float As[8][64];
    __shared__ float Bs[8][64];
    int tid = threadIdx.x;
    int tx = tid & 15, ty = tid >> 4;
    float acc[4][4];
#pragma unroll
    for (int i = 0; i < 4; i++)
#pragma unroll
        for (int j = 0; j < 4; j++) acc[i][j] = 0.f;

    int nkt = (K + 7) >> 3;
    for (int kt = 0; kt < nkt; kt++) {
        int k0 = kt * 8;
#pragma unroll
        for (int i = 0; i < 2; i++) {
            int t = tid * 2 + i;
            int k = t & 7, m = t >> 3;
            float v = 0.f;
            if (row0 + m < M && k0 + k < K)
                v = A[(size_t)(row0 + m) * lda + k0 + k];
            As[k][m] = v;
        }
#pragma unroll
        for (int i = 0; i < 2; i++) {
            int t = tid * 2 + i;
            if (!TRANSB) {
                int k = t >> 6, n = t & 63;
                float v = 0.f;
                if (k0 + k < K && col0 + n < N)
                    v = Bm[(size_t)(k0 + k) * ldb + col0 + n];
                Bs[k][n] = v;
            } else {
                int n = t >> 3, k = t & 7;
                float v = 0.f;
                if (k0 + k < K && col0 + n < N)
                    v = Bm[(size_t)(col0 + n) * ldb + k0 + k];
                Bs[k][n] = v;
            }
        }
        __syncthreads();
#pragma unroll
        for (int k = 0; k < 8; k++) {
            float ar[4], br[4];
            *(float4*)ar = *(const float4*)&As[k][ty * 4];
            *(float4*)br = *(const float4*)&Bs[k][tx * 4];
#pragma unroll
            for (int ii = 0; ii < 4; ii++)
#pragma unroll
                for (int jj = 0; jj < 4; jj++)
                    acc[ii][jj] = fmaf(ar[ii], br[jj], acc[ii][jj]);
        }
        __syncthreads();
    }
#pragma unroll
    for (int ii = 0; ii < 4; ii++) {
        int r = row0 + ty * 4 + ii;
        if (r >= M) continue;
#pragma unroll
        for (int jj = 0; jj < 4; jj++) {
            int c = col0 + tx * 4 + jj;
            if (c >= N) continue;
            float v = acc[ii][jj];
            if (bias) v += bias[c];
            if (EPI == 1) {
                float c0 = e0[(size_t)r * 2 + 0];
                float c1 = e0[(size_t)r * 2 + 1];
                v += c0 * e1[c] + c1 * e1[N + c] + e2[c];
                v = fmaxf(v, 0.f);
            } else if (EPI == 2) {
                v = fmaxf(v, 0.f) + e0[(size_t)r * ldc + c];
            }
            C[(size_t)r * ldc + c] = v;
        }
    }
}

// ---------------- conv over nodes (3-tap along F) + gate ----------------
// cout[bt,n,f] = sum_m cw[n,m,0]*vn[bt,m,f-1] + cw[n,m,1]*vn[bt,m,f] + cw[n,m,2]*vn[bt,m,f+1]
// sg = (cout + conv_b[n] + gate_res) * u
__global__ __launch_bounds__(256)
void conv_gate_kernel(const float* __restrict__ vn,
                      const float* __restrict__ cw,
                      const float* __restrict__ cb,
                      const float* __restrict__ gres,
                      const float* __restrict__ hbuf,   // u at stride 256
                      float* __restrict__ sg)
{
    int bt = blockIdx.y;
    int n0 = blockIdx.x * 64;
    __shared__ float Vs[32][130];
    __shared__ float Cs[64][32][3];
    int tid = threadIdx.x;
    int nl = tid >> 3;      // 0..31 -> rows n0+2*nl, n0+2*nl+1
    int fo = tid & 7;
    float acc0[16], acc1[16];
#pragma unroll
    for (int j = 0; j < 16; j++) { acc0[j] = 0.f; acc1[j] = 0.f; }

    const float* vbt = vn + (size_t)bt * NNODE * 128;
    for (int m0 = 0; m0 < NNODE; m0 += 32) {
        __syncthreads();
        for (int idx = tid; idx < 32 * 130; idx += 256) {
            int mm = idx / 130, ff = idx % 130;
            int m = m0 + mm, f = ff - 1;
            float v = 0.f;
            if (m < NNODE && f >= 0 && f < 128) v = vbt[(size_t)m * 128 + f];
            Vs[mm][ff] = v;
        }
        for (int idx = tid; idx < 64 * 32 * 3; idx += 256) {
            int n_l = idx / 96; int rem = idx % 96;
            int mm = rem / 3, k = rem % 3;
            int n = n0 + n_l, m = m0 + mm;
            Cs[n_l][mm][k] = (n < NNODE && m < NNODE)
                           ? cw[((size_t)n * NNODE + m) * 3 + k] : 0.f;
        }
        __syncthreads();
#pragma unroll 4
        for (int mm = 0; mm < 32; mm++) {
            float c00 = Cs[2*nl][mm][0], c01 = Cs[2*nl][mm][1], c02 = Cs[2*nl][mm][2];
            float c10 = Cs[2*nl+1][mm][0], c11 = Cs[2*nl+1][mm][1], c12 = Cs[2*nl+1][mm][2];
#pragma unroll
            for (int j = 0; j < 16; j++) {
                int f = fo + 8 * j;
                float vm1 = Vs[mm][f];
                float v0  = Vs[mm][f + 1];
                float vp1 = Vs[mm][f + 2];
                acc0[j] += c00 * vm1 + c01 * v0 + c02 * vp1;
                acc1[j] += c10 * vm1 + c11 * v0 + c12 * vp1;
            }
        }
    }
#pragma unroll
    for (int half = 0; half < 2; half++) {
        int n = n0 + 2 * nl + half;
        if (n >= NNODE) continue;
        size_t row = (size_t)bt * NNODE + n;
        float bias = cb[n];
        float* accp = half ? acc1 : acc0;
#pragma unroll
        for (int j = 0; j < 16; j++) {
            int f = fo + 8 * j;
            float g = gres[row * 128 + f];
            float u = hbuf[row * 256 + f];
            sg[row * 128 + f] = (accp[j] + bias + g) * u;
        }
    }
}

// ---------------- host launcher ----------------
extern "C" void kernel_launch(void* const* d_in, const int* in_sizes, int n_in,
                              void* d_out, int out_size)
{
    const float* x      = (const float*)d_in[0];
    const float* norm_g = (const float*)d_in[1];
    const float* norm_b = (const float*)d_in[2];
    const float* W1     = (const float*)d_in[3];
    const float* b1     = (const float*)d_in[4];
    const float* aff1_W = (const float*)d_in[5];
    const float* aff1_b = (const float*)d_in[6];
    const float* Wl     = (const float*)d_in[7];
    const float* bl     = (const float*)d_in[8];
    const float* sgu_g  = (const float*)d_in[9];
    const float* sgu_b  = (const float*)d_in[10];
    const float* conv_w = (const float*)d_in[11];
    const float* conv_b = (const float*)d_in[12];
    const float* Wqkv   = (const float*)d_in[13];
    const float* bqkv   = (const float*)d_in[14];
    const float* Wo     = (const float*)d_in[15];
    const float* bo     = (const float*)d_in[16];
    const float* W2     = (const float*)d_in[17];
    const float* b2     = (const float*)d_in[18];
    float* out = (float*)d_out;

    float *xn, *qkv, *coords, *h, *w, *attnout, *gateres, *vn, *sg;
    cudaGetSymbolAddress((void**)&xn,      g_xn);
    cudaGetSymbolAddress((void**)&qkv,     g_qkv);
    cudaGetSymbolAddress((void**)&coords,  g_coords);
    cudaGetSymbolAddress((void**)&h,       g_h);
    cudaGetSymbolAddress((void**)&w,       g_w);
    cudaGetSymbolAddress((void**)&attnout, g_attnout);
    cudaGetSymbolAddress((void**)&gateres, g_gateres);
    cudaGetSymbolAddress((void**)&vn,      g_vn);
    cudaGetSymbolAddress((void**)&sg,      g_sg);

    const int rowBlocks = (MT + 7) / 8;   // 15600

    // 1) LayerNorm(x) + coords = xn@Wl + bl (fused)
    ln_kernel<<<rowBlocks, 256>>>(x, 128, xn, norm_g, norm_b, MT, coords, Wl, bl);

    // 2) qkv = xn @ Wqkv + bqkv
    {
        dim3 g(6, (MT + 63) / 64, 1);
        sgemm_kernel<false, 0><<<g, 256>>>(xn, 128, 0, Wqkv, 384, 0,
                                           qkv, 384, 0, MT, 384, 128,
                                           bqkv, nullptr, nullptr, nullptr);
    }
    // 3) h = relu(xn @ W1 + b1 + coords @ aff1_W + aff1_b)
    {
        dim3 g(4, (MT + 63) / 64, 1);
        sgemm_kernel<false, 1><<<g, 256>>>(xn, 128, 0, W1, 256, 0,
                                           h, 256, 0, MT, 256, 128,
                                           b1, coords, aff1_W, aff1_b);
    }
    // 4) scores = q @ k^T  (batched over BT)
    {
        dim3 g((NNODE + 63) / 64, (NNODE + 63) / 64, BT);
        sgemm_kernel<true, 0><<<g, 256>>>(qkv, 384, (long long)NNODE * 384,
                                          qkv + 128, 384, (long long)NNODE * 384,
                                          w, NNODE, (long long)NNODE * NNODE,
                                          NNODE, NNODE, 128,
                                          nullptr, nullptr, nullptr, nullptr);
    }
    // 5) softmax rows
    softmax_kernel<<<rowBlocks, 256>>>(w, MT);

    // 6) attnout = w @ v  (batched)
    {
        dim3 g(2, (NNODE + 63) / 64, BT);
        sgemm_kernel<false, 0><<<g, 256>>>(w, NNODE, (long long)NNODE * NNODE,
                                           qkv + 256, 384, (long long)NNODE * 384,
                                           attnout, 128, (long long)NNODE * 128,
                                           NNODE, 128, NNODE,
                                           nullptr, nullptr, nullptr, nullptr);
    }
    // 7) gate_res = attnout @ Wo + bo
    {
        dim3 g(2, (MT + 63) / 64, 1);
        sgemm_kernel<false, 0><<<g, 256>>>(attnout, 128, 0, Wo, 128, 0,
                                           gateres, 128, 0, MT, 128, 128,
                                           bo, nullptr, nullptr, nullptr);
    }
    // 8) vn = LN(vv = h[:,128:256])
    ln_kernel<<<rowBlocks, 256>>>(h + 128, 256, vn, sgu_g, sgu_b, MT,
                                  nullptr, nullptr, nullptr);

    // 9) conv over nodes + bias + gate_res, times u  -> sg
    {
        dim3 g((NNODE + 63) / 64, BT);
        conv_gate_kernel<<<g, 256>>>(vn, conv_w, conv_b, gateres, h, sg);
    }
    // 10) out = relu(sg @ W2 + b2) + x
    {
        dim3 g(2, (MT + 63) / 64, 1);
        sgemm_kernel<false, 2><<<g, 256>>>(sg, 128, 0, W2, 128, 0,
                                           out, 128, 0, MT, 128, 128,
                                           b2, x, nullptr, nullptr);
    }
}

// round 3
// speedup vs baseline: 1.7675x; 1.7675x over previous
#include <cuda_runtime.h>

// ---------------- problem constants ----------------
#define BT  384
#define NN  325
#define MT  (BT*NN)     // 124800

// ---------------- scratch (device globals) ----------------
__device__ float g_xn     [(size_t)MT*128];
__device__ float g_qkv    [(size_t)MT*384];
__device__ float g_coords [(size_t)MT*2];
__device__ float g_h      [(size_t)MT*256];
__device__ float g_w      [(size_t)BT*NN*NN];
__device__ float g_attnout[(size_t)MT*128];
__device__ float g_gateres[(size_t)MT*128];
__device__ float g_vn     [(size_t)MT*128];
__device__ float g_sg     [(size_t)MT*128];
__device__ unsigned g_cwT [3*NN*NN];

// ---------------- helpers ----------------
__device__ __forceinline__ unsigned f2tf(float f) {
    unsigned r;
    asm("cvt.rna.tf32.f32 %0, %1;" : "=r"(r) : "f"(f));
    return r;
}
__device__ __forceinline__ void mma_tf32(float& c0, float& c1, float& c2, float& c3,
                                         unsigned a0, unsigned a1, unsigned a2, unsigned a3,
                                         unsigned b0, unsigned b1) {
    asm volatile("mma.sync.aligned.m16n8k8.row.col.f32.tf32.tf32.f32 "
                 "{%0,%1,%2,%3}, {%4,%5,%6,%7}, {%8,%9}, {%0,%1,%2,%3};\n"
                 : "+f"(c0), "+f"(c1), "+f"(c2), "+f"(c3)
                 : "r"(a0), "r"(a1), "r"(a2), "r"(a3), "r"(b0), "r"(b1));
}

// ---------------- LayerNorm (warp per row, D=128) + optional coords -----
__global__ __launch_bounds__(256)
void ln_kernel(const float* __restrict__ in, int istride,
               float* __restrict__ out,
               const float* __restrict__ gam, const float* __restrict__ bet,
               int nrows,
               float* __restrict__ coords,
               const float* __restrict__ Wl, const float* __restrict__ bl)
{
    int row = blockIdx.x * 8 + (threadIdx.x >> 5);
    if (row >= nrows) return;
    int lane = threadIdx.x & 31;
    float4 v = *(const float4*)(in + (size_t)row * istride + lane * 4);
    float s  = v.x + v.y + v.z + v.w;
    float ss = v.x*v.x + v.y*v.y + v.z*v.z + v.w*v.w;
#pragma unroll
    for (int o = 16; o > 0; o >>= 1) {
        s  += __shfl_xor_sync(0xffffffffu, s,  o);
        ss += __shfl_xor_sync(0xffffffffu, ss, o);
    }
    float mean = s * (1.f/128.f);
    float var  = ss * (1.f/128.f) - mean * mean;
    float r = rsqrtf(var + 1e-5f);
    int c = lane * 4;
    float o0 = (v.x - mean) * r * gam[c+0] + bet[c+0];
    float o1 = (v.y - mean) * r * gam[c+1] + bet[c+1];
    float o2 = (v.z - mean) * r * gam[c+2] + bet[c+2];
    float o3 = (v.w - mean) * r * gam[c+3] + bet[c+3];
    *(float4*)(out + (size_t)row * 128 + c) = make_float4(o0, o1, o2, o3);
    if (coords) {
        float c0 = o0*Wl[(c+0)*2] + o1*Wl[(c+1)*2] + o2*Wl[(c+2)*2] + o3*Wl[(c+3)*2];
        float c1 = o0*Wl[(c+0)*2+1] + o1*Wl[(c+1)*2+1] + o2*Wl[(c+2)*2+1] + o3*Wl[(c+3)*2+1];
#pragma unroll
        for (int o = 16; o > 0; o >>= 1) {
            c0 += __shfl_xor_sync(0xffffffffu, c0, o);
            c1 += __shfl_xor_sync(0xffffffffu, c1, o);
        }
        if (lane == 0) {
            coords[(size_t)row*2 + 0] = c0 + bl[0];
            coords[(size_t)row*2 + 1] = c1 + bl[1];
        }
    }
}

// ---------------- softmax over rows of length 325 (warp per row) --------
__global__ __launch_bounds__(256)
void softmax_kernel(float* __restrict__ w, int nrows)
{
    int row = blockIdx.x * 8 + (threadIdx.x >> 5);
    if (row >= nrows) return;
    int lane = threadIdx.x & 31;
    float* p = w + (size_t)row * NN;
    float v[11];
    float mx = -1e30f;
#pragma unroll
    for (int i = 0; i < 11; i++) {
        int idx = lane + 32 * i;
        v[i] = (idx < NN) ? p[idx] : -1e30f;
        mx = fmaxf(mx, v[i]);
    }
#pragma unroll
    for (int o = 16; o > 0; o >>= 1)
        mx = fmaxf(mx, __shfl_xor_sync(0xffffffffu, mx, o));
    float s = 0.f;
#pragma unroll
    for (int i = 0; i < 11; i++) { v[i] = __expf(v[i] - mx); s += v[i]; }
#pragma unroll
    for (int o = 16; o > 0; o >>= 1)
        s += __shfl_xor_sync(0xffffffffu, s, o);
    float inv = 1.f / s;
#pragma unroll
    for (int i = 0; i < 11; i++) {
        int idx = lane + 32 * i;
        if (idx < NN) p[idx] = v[i] * inv;
    }
}

// ---------------- cw transpose to [tap][m][n], tf32-encoded -------------
__global__ __launch_bounds__(256)
void cwt_kernel(const float* __restrict__ cw, unsigned* __restrict__ cwT)
{
    int idx = blockIdx.x * 256 + threadIdx.x;
    if (idx >= 3 * NN * NN) return;
    int tap = idx / (NN * NN);
    int rem = idx % (NN * NN);
    int m = rem / NN, n = rem % NN;
    cwT[idx] = f2tf(cw[((size_t)n * NN + m) * 3 + tap]);
}

// ---------------- tf32 tensor-core GEMM, 128x128 tile, BK=32 ------------
// EPI: 0 = +bias ; 1 = +bias + coords-affine + ReLU ; 2 = +bias, ReLU, +residual
template<bool TRANSB, int EPI>
__global__ __launch_bounds__(256, 2)
void gemm_tc(const float* __restrict__ A, int lda, long long sA,
             const float* __restrict__ B, int ldb, long long sB,
             float* __restrict__ C, int ldc, long long sC,
             int M, int N, int K,
             const float* __restrict__ bias,
             const float* __restrict__ e0, const float* __restrict__ e1,
             const float* __restrict__ e2)
{
    __shared__ unsigned As[32][136];
    __shared__ unsigned Bs[32][136];
    A += (long long)blockIdx.z * sA;
    B += (long long)blockIdx.z * sB;
    C += (long long)blockIdx.z * sC;
    const int row0 = blockIdx.y * 128, col0 = blockIdx.x * 128;
    const int tid = threadIdx.x, lane = tid & 31, wid = tid >> 5;
    const int wm = wid >> 1, wn = wid & 1;
    const int qg = lane >> 2, rg = lane & 3;
    float acc[2][8][4];
#pragma unroll
    for (int a = 0; a < 2; a++)
#pragma unroll
        for (int b = 0; b < 8; b++)
#pragma unroll
            for (int c = 0; c < 4; c++) acc[a][b][c] = 0.f;

    const int am = tid & 127, ah = (tid >> 7) * 16;
    const bool avec = ((lda & 3) == 0);
    const int gr = row0 + am;
    const int gc = col0 + am;

    for (int k0 = 0; k0 < K; k0 += 32) {
        __syncthreads();
        // ---- A tile: As[k][m] = A[row0+m][k0+k] ----
#pragma unroll
        for (int i = 0; i < 4; i++) {
            int kk = ah + i * 4;
            int gk = k0 + kk;
            unsigned v0 = 0, v1 = 0, v2 = 0, v3 = 0;
            if (gr < M) {
                if (avec && gk + 3 < K) {
                    float4 t = *(const float4*)(A + (size_t)gr * lda + gk);
                    v0 = f2tf(t.x); v1 = f2tf(t.y); v2 = f2tf(t.z); v3 = f2tf(t.w);
                } else {
                    const float* p = A + (size_t)gr * lda;
                    if (gk     < K) v0 = f2tf(p[gk]);
                    if (gk + 1 < K) v1 = f2tf(p[gk + 1]);
                    if (gk + 2 < K) v2 = f2tf(p[gk + 2]);
                    if (gk + 3 < K) v3 = f2tf(p[gk + 3]);
                }
            }
            As[kk][am] = v0; As[kk+1][am] = v1; As[kk+2][am] = v2; As[kk+3][am] = v3;
        }
        // ---- B tile: Bs[k][n] ----
        if (!TRANSB) {
#pragma unroll
            for (int i = 0; i < 16; i++) {
                int kk = ah + i;
                int gk = k0 + kk;
                unsigned v = 0;
                if (gc < N && gk < K) v = f2tf(B[(size_t)gk * ldb + gc]);
                Bs[kk][am] = v;
            }
        } else {
            const bool bvec = ((ldb & 3) == 0);
#pragma unroll
            for (int i = 0; i < 4; i++) {
                int kk = ah + i * 4;
                int gk = k0 + kk;
                unsigned v0 = 0, v1 = 0, v2 = 0, v3 = 0;
                if (gc < N) {
                    if (bvec && gk + 3 < K) {
                        float4 t = *(const float4*)(B + (size_t)gc * ldb + gk);
                        v0 = f2tf(t.x); v1 = f2tf(t.y); v2 = f2tf(t.z); v3 = f2tf(t.w);
                    } else {
                        const float* p = B + (size_t)gc * ldb;
                        if (gk     < K) v0 = f2tf(p[gk]);
                        if (gk + 1 < K) v1 = f2tf(p[gk + 1]);
                        if (gk + 2 < K) v2 = f2tf(p[gk + 2]);
                        if (gk + 3 < K) v3 = f2tf(p[gk + 3]);
                    }
                }
                Bs[kk][am] = v0; Bs[kk+1][am] = v1; Bs[kk+2][am] = v2; Bs[kk+3][am] = v3;
            }
        }
        __syncthreads();
        // ---- compute ----
#pragma unroll
        for (int ks = 0; ks < 4; ks++) {
            int kk = ks * 8;
            unsigned af[2][4], bf[8][2];
#pragma unroll
            for (int mt = 0; mt < 2; mt++) {
                int r = wm * 32 + mt * 16 + qg;
                af[mt][0] = As[kk + rg][r];
                af[mt][1] = As[kk + rg][r + 8];
                af[mt][2] = As[kk + rg + 4][r];
                af[mt][3] = As[kk + rg + 4][r + 8];
            }
#pragma unroll
            for (int nt = 0; nt < 8; nt++) {
                int c = wn * 64 + nt * 8 + qg;
                bf[nt][0] = Bs[kk + rg][c];
                bf[nt][1] = Bs[kk + rg + 4][c];
            }
#pragma unroll
            for (int mt = 0; mt < 2; mt++)
#pragma unroll
                for (int nt = 0; nt < 8; nt++)
                    mma_tf32(acc[mt][nt][0], acc[mt][nt][1], acc[mt][nt][2], acc[mt][nt][3],
                             af[mt][0], af[mt][1], af[mt][2], af[mt][3],
                             bf[nt][0], bf[nt][1]);
        }
    }
    // ---- epilogue ----
#pragma unroll
    for (int mt = 0; mt < 2; mt++) {
#pragma unroll
        for (int i2 = 0; i2 < 2; i2++) {
            int r = row0 + wm * 32 + mt * 16 + qg + i2 * 8;
            if (r >= M) continue;
#pragma unroll
            for (int nt = 0; nt < 8; nt++) {
#pragma unroll
                for (int j = 0; j < 2; j++) {
                    int c = col0 + wn * 64 + nt * 8 + rg * 2 + j;
                    if (c >= N) continue;
                    float v = acc[mt][nt][i2 * 2 + j];
                    if (bias) v += bias[c];
                    if (EPI == 1) {
                        v += e0[(size_t)r * 2] * e1[c] + e0[(size_t)r * 2 + 1] * e1[N + c] + e2[c];
                        v = fmaxf(v, 0.f);
                    } else if (EPI == 2) {
                        v = fmaxf(v, 0.f) + e0[(size_t)r * ldc + c];
                    }
                    C[(size_t)r * ldc + c] = v;
                }
            }
        }
    }
}

// ---------------- conv as tensor-core GEMM + fused gate -----------------
// sg[bt,n,f] = (sum_tap sum_m cwT[tap][m][n]*vn[bt,m,f+tap-1] + cb[n] + gres) * u
__global__ __launch_bounds__(256, 2)
void conv_tc(const float* __restrict__ vn, const unsigned* __restrict__ cwT,
             const float* __restrict__ cb, const float* __restrict__ gres,
             const float* __restrict__ hbuf, float* __restrict__ sg)
{
    __shared__ unsigned As[32][136];
    __shared__ unsigned Bs[32][136];
    const int bt = blockIdx.y, n0 = blockIdx.x * 128;
    const float* vbt = vn + (size_t)bt * NN * 128;
    const int tid = threadIdx.x, lane = tid & 31, wid = tid >> 5;
    const int wm = wid >> 1, wn = wid & 1;
    const int qg = lane >> 2, rg = lane & 3;
    float acc[2][8][4];
#pragma unroll
    for (int a = 0; a < 2; a++)
#pragma unroll
        for (int b = 0; b < 8; b++)
#pragma unroll
            for (int c = 0; c < 4; c++) acc[a][b][c] = 0.f;

    const int an = tid & 127, ah = (tid >> 7) * 16;
    const bool anok = (n0 + an < NN);

    for (int tap = 0; tap < 3; tap++) {
        const int shift = tap - 1;
        const unsigned* cwt = cwT + (size_t)tap * NN * NN;
        const int fsh = an + shift;
        const bool fok = (fsh >= 0 && fsh < 128);
        for (int m0 = 0; m0 < NN; m0 += 32) {
            __syncthreads();
#pragma unroll
            for (int i = 0; i < 16; i++) {
                int mm = ah + i, gm = m0 + mm;
                unsigned va = 0, vb = 0;
                if (gm < NN) {
                    if (anok) va = cwt[(size_t)gm * NN + n0 + an];
                    if (fok)  vb = f2tf(vbt[(size_t)gm * 128 + fsh]);
                }
                As[mm][an] = va;
                Bs[mm][an] = vb;
            }
            __syncthreads();
#pragma unroll
            for (int ks = 0; ks < 4; ks++) {
                int kk = ks * 8;
                unsigned af[2][4], bf[8][2];
#pragma unroll
                for (int mt = 0; mt < 2; mt++) {
                    int r = wm * 32 + mt * 16 + qg;
                    af[mt][0] = As[kk + rg][r];
                    af[mt][1] = As[kk + rg][r + 8];
                    af[mt][2] = As[kk + rg + 4][r];
                    af[mt][3] = As[kk + rg + 4][r + 8];
                }
#pragma unroll
                for (int nt = 0; nt < 8; nt++) {
                    int c = wn * 64 + nt * 8 + qg;
                    bf[nt][0] = Bs[kk + rg][c];
                    bf[nt][1] = Bs[kk + rg + 4][c];
                }
#pragma unroll
                for (int mt = 0; mt < 2; mt++)
#pragma unroll
                    for (int nt = 0; nt < 8; nt++)
                        mma_tf32(acc[mt][nt][0], acc[mt][nt][1], acc[mt][nt][2], acc[mt][nt][3],
                                 af[mt][0], af[mt][1], af[mt][2], af[mt][3],
                                 bf[nt][0], bf[nt][1]);
            }
        }
    }
    // epilogue: (acc + cb[n] + gres) * u
#pragma unroll
    for (int mt = 0; mt < 2; mt++) {
#pragma unroll
        for (int i2 = 0; i2 < 2; i2++) {
            int n = n0 + wm * 32 + mt * 16 + qg + i2 * 8;
            if (n >= NN) continue;
            size_t row = (size_t)bt * NN + n;
            float bias = cb[n];
#pragma unroll
            for (int nt = 0; nt < 8; nt++) {
#pragma unroll
                for (int j = 0; j < 2; j++) {
                    int f = wn * 64 + nt * 8 + rg * 2 + j;
                    float v = acc[mt][nt][i2 * 2 + j] + bias + gres[row * 128 + f];
                    sg[row * 128 + f] = v * hbuf[row * 256 + f];
                }
            }
        }
    }
}

// ---------------- host launcher ----------------
extern "C" void kernel_launch(void* const* d_in, const int* in_sizes, int n_in,
                              void* d_out, int out_size)
{
    const float* x      = (const float*)d_in[0];
    const float* norm_g = (const float*)d_in[1];
    const float* norm_b = (const float*)d_in[2];
    const float* W1     = (const float*)d_in[3];
    const float* b1     = (const float*)d_in[4];
    const float* aff1_W = (const float*)d_in[5];
    const float* aff1_b = (const float*)d_in[6];
    const float* Wl     = (const float*)d_in[7];
    const float* bl     = (const float*)d_in[8];
    const float* sgu_g  = (const float*)d_in[9];
    const float* sgu_b  = (const float*)d_in[10];
    const float* conv_w = (const float*)d_in[11];
    const float* conv_b = (const float*)d_in[12];
    const float* Wqkv   = (const float*)d_in[13];
    const float* bqkv   = (const float*)d_in[14];
    const float* Wo     = (const float*)d_in[15];
    const float* bo     = (const float*)d_in[16];
    const float* W2     = (const float*)d_in[17];
    const float* b2     = (const float*)d_in[18];
    float* out = (float*)d_out;

    float *xn, *qkv, *coords, *h, *w, *attnout, *gateres, *vn, *sg;
    unsigned* cwT;
    cudaGetSymbolAddress((void**)&xn,      g_xn);
    cudaGetSymbolAddress((void**)&qkv,     g_qkv);
    cudaGetSymbolAddress((void**)&coords,  g_coords);
    cudaGetSymbolAddress((void**)&h,       g_h);
    cudaGetSymbolAddress((void**)&w,       g_w);
    cudaGetSymbolAddress((void**)&attnout, g_attnout);
    cudaGetSymbolAddress((void**)&gateres, g_gateres);
    cudaGetSymbolAddress((void**)&vn,      g_vn);
    cudaGetSymbolAddress((void**)&sg,      g_sg);
    cudaGetSymbolAddress((void**)&cwT,     g_cwT);

    const int rowBlocks = (MT + 7) / 8;

    // 0) transpose conv weights (independent of the rest)
    cwt_kernel<<<(3 * NN * NN + 255) / 256, 256>>>(conv_w, cwT);

    // 1) LayerNorm(x) + coords (fused)
    ln_kernel<<<rowBlocks, 256>>>(x, 128, xn, norm_g, norm_b, MT, coords, Wl, bl);

    // 2) qkv = xn @ Wqkv + bqkv
    {
        dim3 g(3, 975, 1);
        gemm_tc<false, 0><<<g, 256>>>(xn, 128, 0, Wqkv, 384, 0,
                                      qkv, 384, 0, MT, 384, 128,
                                      bqkv, nullptr, nullptr, nullptr);
    }
    // 3) h = relu(xn @ W1 + b1 + coords @ aff1_W + aff1_b)
    {
        dim3 g(2, 975, 1);
        gemm_tc<false, 1><<<g, 256>>>(xn, 128, 0, W1, 256, 0,
                                      h, 256, 0, MT, 256, 128,
                                      b1, coords, aff1_W, aff1_b);
    }
    // 4) scores = q @ k^T  (batched over BT)
    {
        dim3 g(3, 3, BT);
        gemm_tc<true, 0><<<g, 256>>>(qkv, 384, (long long)NN * 384,
                                     qkv + 128, 384, (long long)NN * 384,
                                     w, NN, (long long)NN * NN,
                                     NN, NN, 128,
                                     nullptr, nullptr, nullptr, nullptr);
    }
    // 5) softmax
    softmax_kernel<<<rowBlocks, 256>>>(w, MT);

    // 6) attnout = w @ v  (batched)
    {
        dim3 g(1, 3, BT);
        gemm_tc<false, 0><<<g, 256>>>(w, NN, (long long)NN * NN,
                                      qkv + 256, 384, (long long)NN * 384,
                                      attnout, 128, (long long)NN * 128,
                                      NN, 128, NN,
                                      nullptr, nullptr, nullptr, nullptr);
    }
    // 7) gate_res = attnout @ Wo + bo
    {
        dim3 g(1, 975, 1);
        gemm_tc<false, 0><<<g, 256>>>(attnout, 128, 0, Wo, 128, 0,
                                      gateres, 128, 0, MT, 128, 128,
                                      bo, nullptr, nullptr, nullptr);
    }
    // 8) vn = LN(h[:,128:256])
    ln_kernel<<<rowBlocks, 256>>>(h + 128, 256, vn, sgu_g, sgu_b, MT,
                                  nullptr, nullptr, nullptr);

    // 9) conv (tensor cores) + bias + gate, times u -> sg
    {
        dim3 g(3, BT);
        conv_tc<<<g, 256>>>(vn, cwT, conv_b, gateres, h, sg);
    }
    // 10) out = relu(sg @ W2 + b2) + x
    {
        dim3 g(1, 975, 1);
        gemm_tc<false, 2><<<g, 256>>>(sg, 128, 0, W2, 128, 0,
                                      out, 128, 0, MT, 128, 128,
                                      b2, x, nullptr, nullptr);
    }
}

// round 4
// speedup vs baseline: 3.5245x; 1.9940x over previous
#include <cuda_runtime.h>
#include <cstdint>

#define BT 384
#define NN 325
#define MT (BT*NN)     // 124800

// ---------------- scratch ----------------
__device__ float g_xn     [(size_t)MT*128];
__device__ float g_qkv    [(size_t)MT*384];
__device__ float g_coords [(size_t)MT*2];
__device__ float g_h      [(size_t)MT*256];
__device__ float g_attnout[(size_t)MT*128];
__device__ float g_gateres[(size_t)MT*128];
__device__ float g_vn     [(size_t)MT*128];
__device__ float g_sg     [(size_t)MT*128];
__device__ float g_wqkv   [128*384];
__device__ float g_w1     [128*256];
__device__ float g_wo     [128*128];
__device__ float g_w2     [128*128];
__device__ float g_cw     [325*992];    // conv_w rows padded 975->992, rounded

// ---------------- helpers ----------------
__device__ __forceinline__ float rnd_tf32(float f) {
    unsigned u;
    asm("cvt.rna.tf32.f32 %0, %1;" : "=r"(u) : "f"(f));
    return __uint_as_float(u);
}
__device__ __forceinline__ unsigned sptr(const void* p) {
    return (unsigned)__cvta_generic_to_shared(p);
}
__device__ __forceinline__ void cp16(unsigned dst, const void* src, bool pred) {
    int sz = pred ? 16 : 0;
    asm volatile("cp.async.ca.shared.global [%0], [%1], 16, %2;\n"
                 :: "r"(dst), "l"(src), "r"(sz));
}
__device__ __forceinline__ void cp4(unsigned dst, const void* src, bool pred) {
    int sz = pred ? 4 : 0;
    asm volatile("cp.async.ca.shared.global [%0], [%1], 4, %2;\n"
                 :: "r"(dst), "l"(src), "r"(sz));
}
#define CP_COMMIT() asm volatile("cp.async.commit_group;\n")
#define CP_WAIT(n)  asm volatile("cp.async.wait_group %0;\n" :: "n"(n))

__device__ __forceinline__ void mma_tf32(float& c0, float& c1, float& c2, float& c3,
                                         float a0, float a1, float a2, float a3,
                                         float b0, float b1) {
    asm volatile("mma.sync.aligned.m16n8k8.row.col.f32.tf32.tf32.f32 "
                 "{%0,%1,%2,%3}, {%4,%5,%6,%7}, {%8,%9}, {%0,%1,%2,%3};\n"
                 : "+f"(c0), "+f"(c1), "+f"(c2), "+f"(c3)
                 : "r"(__float_as_uint(a0)), "r"(__float_as_uint(a1)),
                   "r"(__float_as_uint(a2)), "r"(__float_as_uint(a3)),
                   "r"(__float_as_uint(b0)), "r"(__float_as_uint(b1)));
}

// ---------------- weight rounding prep ----------------
__global__ __launch_bounds__(256)
void prep_kernel(const float* __restrict__ wqkv, const float* __restrict__ w1,
                 const float* __restrict__ wo, const float* __restrict__ w2,
                 const float* __restrict__ cw,
                 float* __restrict__ oq, float* __restrict__ o1,
                 float* __restrict__ oo, float* __restrict__ o2,
                 float* __restrict__ ocw)
{
    int i = blockIdx.x * 256 + threadIdx.x;
    if (i < 49152) { oq[i] = rnd_tf32(wqkv[i]); return; }
    i -= 49152;
    if (i < 32768) { o1[i] = rnd_tf32(w1[i]); return; }
    i -= 32768;
    if (i < 16384) { oo[i] = rnd_tf32(wo[i]); return; }
    i -= 16384;
    if (i < 16384) { o2[i] = rnd_tf32(w2[i]); return; }
    i -= 16384;
    if (i < 325 * 992) {
        int n = i / 992, k = i % 992;
        ocw[i] = (k < 975) ? rnd_tf32(cw[n * 975 + k]) : 0.f;
    }
}

// ---------------- LayerNorm + optional coords; rounds output ------------
__global__ __launch_bounds__(256)
void ln_kernel(const float* __restrict__ in, int istride,
               float* __restrict__ out,
               const float* __restrict__ gam, const float* __restrict__ bet,
               int nrows,
               float* __restrict__ coords,
               const float* __restrict__ Wl, const float* __restrict__ bl)
{
    int row = blockIdx.x * 8 + (threadIdx.x >> 5);
    if (row >= nrows) return;
    int lane = threadIdx.x & 31;
    float4 v = *(const float4*)(in + (size_t)row * istride + lane * 4);
    float s  = v.x + v.y + v.z + v.w;
    float ss = v.x*v.x + v.y*v.y + v.z*v.z + v.w*v.w;
#pragma unroll
    for (int o = 16; o > 0; o >>= 1) {
        s  += __shfl_xor_sync(0xffffffffu, s,  o);
        ss += __shfl_xor_sync(0xffffffffu, ss, o);
    }
    float mean = s * (1.f/128.f);
    float var  = ss * (1.f/128.f) - mean * mean;
    float r = rsqrtf(var + 1e-5f);
    int c = lane * 4;
    float o0 = (v.x - mean) * r * gam[c+0] + bet[c+0];
    float o1 = (v.y - mean) * r * gam[c+1] + bet[c+1];
    float o2 = (v.z - mean) * r * gam[c+2] + bet[c+2];
    float o3 = (v.w - mean) * r * gam[c+3] + bet[c+3];
    *(float4*)(out + (size_t)row * 128 + c) =
        make_float4(rnd_tf32(o0), rnd_tf32(o1), rnd_tf32(o2), rnd_tf32(o3));
    if (coords) {
        float c0 = o0*Wl[(c+0)*2] + o1*Wl[(c+1)*2] + o2*Wl[(c+2)*2] + o3*Wl[(c+3)*2];
        float c1 = o0*Wl[(c+0)*2+1] + o1*Wl[(c+1)*2+1] + o2*Wl[(c+2)*2+1] + o3*Wl[(c+3)*2+1];
#pragma unroll
        for (int o = 16; o > 0; o >>= 1) {
            c0 += __shfl_xor_sync(0xffffffffu, c0, o);
            c1 += __shfl_xor_sync(0xffffffffu, c1, o);
        }
        if (lane == 0) {
            coords[(size_t)row*2 + 0] = c0 + bl[0];
            coords[(size_t)row*2 + 1] = c1 + bl[1];
        }
    }
}

// ---------------- dense GEMM: M=124800, K=128, tile 128x128 -------------
// A [M][128] rounded; B [128][Ntot] rounded; col slice = blockIdx.x*128.
// EPI: 0 +bias ; 1 +bias+coord-affine+ReLU ; 2 +bias,ReLU,+residual
template<int EPI, bool RND>
__global__ __launch_bounds__(256)
void gemm128(const float* __restrict__ A, const float* __restrict__ B, int ldb,
             float* __restrict__ C, int ldc, int Ntot,
             const float* __restrict__ bias,
             const float* __restrict__ e0, const float* __restrict__ e1,
             const float* __restrict__ e2)
{
    extern __shared__ float sm[];
    float* Bs = sm;               // [128][136]
    float* As = sm + 128*136;     // [2][128][36]
    const int tid = threadIdx.x;
    const int row0 = blockIdx.y * 128, col0 = blockIdx.x * 128;

    // B slice: 128 rows x 128 cols, once
    {
        const float* Bp = B + col0;
#pragma unroll
        for (int i = 0; i < 16; i++) {
            int lin = tid + 256 * i;
            int r = lin >> 5, ch = lin & 31;
            cp16(sptr(Bs + r*136 + ch*4), Bp + (size_t)r*ldb + ch*4, true);
        }
    }
    CP_COMMIT();
#define LOAD_A(stage, k0) do {                                               \
        float* dst = As + (stage)*128*36;                                    \
        _Pragma("unroll")                                                    \
        for (int i = 0; i < 4; i++) {                                        \
            int lin = tid + 256*i;                                           \
            int r = lin >> 3, ch = lin & 7;                                  \
            cp16(sptr(dst + r*36 + ch*4),                                    \
                 A + (size_t)(row0 + r)*128 + (k0) + ch*4, true);            \
        }                                                                    \
        CP_COMMIT();                                                         \
    } while (0)
    LOAD_A(0, 0);
    LOAD_A(1, 32);
    CP_WAIT(1);
    __syncthreads();

    const int lane = tid & 31, wid = tid >> 5;
    const int wm = wid >> 1, wn = wid & 1;
    const int qg = lane >> 2, rg = lane & 3;
    float acc[2][8][4];
#pragma unroll
    for (int a = 0; a < 2; a++)
#pragma unroll
        for (int b = 0; b < 8; b++)
#pragma unroll
            for (int c = 0; c < 4; c++) acc[a][b][c] = 0.f;

    for (int kt = 0; kt < 4; kt++) {
        const float* Ac = As + (kt & 1) * 128 * 36;
#pragma unroll
        for (int ks = 0; ks < 4; ks++) {
            int kk = ks * 8;
            int kg = kt * 32 + kk;
            float af[2][4], bf[8][2];
#pragma unroll
            for (int mt = 0; mt < 2; mt++) {
                int r = wm*32 + mt*16 + qg;
                af[mt][0] = Ac[(r)    *36 + kk + rg];
                af[mt][1] = Ac[(r + 8)*36 + kk + rg];
                af[mt][2] = Ac[(r)    *36 + kk + rg + 4];
                af[mt][3] = Ac[(r + 8)*36 + kk + rg + 4];
            }
#pragma unroll
            for (int nt = 0; nt < 8; nt++) {
                int c = wn*64 + nt*8 + qg;
                bf[nt][0] = Bs[(kg + rg)    *136 + c];
                bf[nt][1] = Bs[(kg + rg + 4)*136 + c];
            }
#pragma unroll
            for (int mt = 0; mt < 2; mt++)
#pragma unroll
                for (int nt = 0; nt < 8; nt++)
                    mma_tf32(acc[mt][nt][0], acc[mt][nt][1], acc[mt][nt][2], acc[mt][nt][3],
                             af[mt][0], af[mt][1], af[mt][2], af[mt][3],
                             bf[nt][0], bf[nt][1]);
        }
        if (kt < 2) {
            __syncthreads();
            LOAD_A(kt & 1, (kt + 2) * 32);
            CP_WAIT(1);
            __syncthreads();
        } else if (kt == 2) {
            CP_WAIT(0);
            __syncthreads();
        }
    }
#undef LOAD_A
    // epilogue
#pragma unroll
    for (int mt = 0; mt < 2; mt++) {
#pragma unroll
        for (int i2 = 0; i2 < 2; i2++) {
            int r = row0 + wm*32 + mt*16 + qg + i2*8;
            float c0v = 0.f, c1v = 0.f;
            if (EPI == 1) { c0v = e0[(size_t)r*2]; c1v = e0[(size_t)r*2 + 1]; }
#pragma unroll
            for (int nt = 0; nt < 8; nt++) {
#pragma unroll
                for (int j = 0; j < 2; j++) {
                    int c = col0 + wn*64 + nt*8 + rg*2 + j;
                    float v = acc[mt][nt][i2*2 + j];
                    if (bias) v += bias[c];
                    if (EPI == 1) {
                        v += c0v * e1[c] + c1v * e1[Ntot + c] + e2[c];
                        v = fmaxf(v, 0.f);
                    } else if (EPI == 2) {
                        v = fmaxf(v, 0.f) + e0[(size_t)r * ldc + c];
                    }
                    if (RND) v = rnd_tf32(v);
                    C[(size_t)r * ldc + c] = v;
                }
            }
        }
    }
}

// ---------------- fused flash attention: grid (3, BT) -------------------
__global__ __launch_bounds__(256)
void attn_kernel(const float* __restrict__ qkv, float* __restrict__ attnout)
{
    extern __shared__ float sm[];
    float* qs   = sm;                     // [128][132]
    float* ks   = sm + 128*132;           // [128][132], reused as P
    float* vs   = sm + 2*128*132;         // [128][136]
    float* lsum = sm + 2*128*132 + 128*136;  // [128][2]
    const int bt = blockIdx.y, q0 = blockIdx.x * 128;
    const int tid = threadIdx.x;
    const float* base = qkv + (size_t)bt * NN * 384;

#define LOAD_QKV(dst, stridew, off, r0) do {                                 \
        _Pragma("unroll")                                                    \
        for (int i = 0; i < 16; i++) {                                       \
            int lin = tid + 256*i;                                           \
            int r = lin >> 5, ch = lin & 31;                                 \
            bool p = ((r0) + r) < NN;                                        \
            cp16(sptr((dst) + r*(stridew) + ch*4),                           \
                 base + (size_t)((r0) + r)*384 + (off) + ch*4, p);           \
        }                                                                    \
    } while (0)

    LOAD_QKV(qs, 132, 0,   q0);
    LOAD_QKV(ks, 132, 128, 0);
    LOAD_QKV(vs, 136, 256, 0);
    CP_COMMIT();
    lsum[tid] = 0.f;   // 256 = 128*2 slots
    CP_WAIT(0);
    __syncthreads();

    const int lane = tid & 31, wid = tid >> 5;
    const int wm = wid >> 1, wn = wid & 1;
    const int qg = lane >> 2, rg = lane & 3;
    float Oacc[2][8][4];
#pragma unroll
    for (int a = 0; a < 2; a++)
#pragma unroll
        for (int b = 0; b < 8; b++)
#pragma unroll
            for (int c = 0; c < 4; c++) Oacc[a][b][c] = 0.f;

    for (int it = 0; it < 3; it++) {
        const int k0g = it * 128;
        float S[2][8][4];
#pragma unroll
        for (int a = 0; a < 2; a++)
#pragma unroll
            for (int b = 0; b < 8; b++)
#pragma unroll
                for (int c = 0; c < 4; c++) S[a][b][c] = 0.f;
        // S = q @ k^T
#pragma unroll
        for (int ks8 = 0; ks8 < 16; ks8++) {
            int kk = ks8 * 8;
            float af[2][4], bf[8][2];
#pragma unroll
            for (int mt = 0; mt < 2; mt++) {
                int r = wm*32 + mt*16 + qg;
                af[mt][0] = qs[(r)    *132 + kk + rg];
                af[mt][1] = qs[(r + 8)*132 + kk + rg];
                af[mt][2] = qs[(r)    *132 + kk + rg + 4];
                af[mt][3] = qs[(r + 8)*132 + kk + rg + 4];
            }
#pragma unroll
            for (int nt = 0; nt < 8; nt++) {
                int c = wn*64 + nt*8 + qg;
                bf[nt][0] = ks[(c)*132 + kk + rg];
                bf[nt][1] = ks[(c)*132 + kk + rg + 4];
            }
#pragma unroll
            for (int mt = 0; mt < 2; mt++)
#pragma unroll
                for (int nt = 0; nt < 8; nt++)
                    mma_tf32(S[mt][nt][0], S[mt][nt][1], S[mt][nt][2], S[mt][nt][3],
                             af[mt][0], af[mt][1], af[mt][2], af[mt][3],
                             bf[nt][0], bf[nt][1]);
        }
        // P = exp(S) masked, row-sums
        float rs[2][2] = {{0.f, 0.f}, {0.f, 0.f}};
#pragma unroll
        for (int mt = 0; mt < 2; mt++)
#pragma unroll
            for (int nt = 0; nt < 8; nt++)
#pragma unroll
                for (int idx = 0; idx < 4; idx++) {
                    int col = k0g + wn*64 + nt*8 + rg*2 + (idx & 1);
                    float p = (col < NN) ? rnd_tf32(__expf(S[mt][nt][idx])) : 0.f;
                    S[mt][nt][idx] = p;
                    rs[mt][idx >> 1] += p;
                }
#pragma unroll
        for (int mt = 0; mt < 2; mt++)
#pragma unroll
            for (int i2 = 0; i2 < 2; i2++) {
                float r = rs[mt][i2];
                r += __shfl_xor_sync(0xffffffffu, r, 1);
                r += __shfl_xor_sync(0xffffffffu, r, 2);
                if (rg == 0)
                    lsum[(wm*32 + mt*16 + qg + i2*8)*2 + wn] += r;
            }
        __syncthreads();   // all S reads of ks done
        // write P into ks buffer ([qrow][key] stride 132)
#pragma unroll
        for (int mt = 0; mt < 2; mt++)
#pragma unroll
            for (int nt = 0; nt < 8; nt++)
#pragma unroll
                for (int idx = 0; idx < 4; idx++) {
                    int r = wm*32 + mt*16 + qg + (idx >> 1)*8;
                    int c = wn*64 + nt*8 + rg*2 + (idx & 1);
                    ks[r*132 + c] = S[mt][nt][idx];
                }
        __syncthreads();
        // O += P @ v
#pragma unroll
        for (int ks8 = 0; ks8 < 16; ks8++) {
            int kk = ks8 * 8;
            float af[2][4], bf[8][2];
#pragma unroll
            for (int mt = 0; mt < 2; mt++) {
                int r = wm*32 + mt*16 + qg;
                af[mt][0] = ks[(r)    *132 + kk + rg];
                af[mt][1] = ks[(r + 8)*132 + kk + rg];
                af[mt][2] = ks[(r)    *132 + kk + rg + 4];
                af[mt][3] = ks[(r + 8)*132 + kk + rg + 4];
            }
#pragma unroll
            for (int nt = 0; nt < 8; nt++) {
                int c = wn*64 + nt*8 + qg;
                bf[nt][0] = vs[(kk + rg)    *136 + c];
                bf[nt][1] = vs[(kk + rg + 4)*136 + c];
            }
#pragma unroll
            for (int mt = 0; mt < 2; mt++)
#pragma unroll
                for (int nt = 0; nt < 8; nt++)
                    mma_tf32(Oacc[mt][nt][0], Oacc[mt][nt][1], Oacc[mt][nt][2], Oacc[mt][nt][3],
                             af[mt][0], af[mt][1], af[mt][2], af[mt][3],
                             bf[nt][0], bf[nt][1]);
        }
        __syncthreads();
        if (it < 2) {
            LOAD_QKV(ks, 132, 128, (it + 1) * 128);
            LOAD_QKV(vs, 136, 256, (it + 1) * 128);
            CP_COMMIT();
            CP_WAIT(0);
            __syncthreads();
        }
    }
#undef LOAD_QKV
    // epilogue: O / l
#pragma unroll
    for (int mt = 0; mt < 2; mt++)
#pragma unroll
        for (int i2 = 0; i2 < 2; i2++) {
            int rl = wm*32 + mt*16 + qg + i2*8;
            int n = q0 + rl;
            if (n >= NN) continue;
            float inv = 1.f / (lsum[rl*2] + lsum[rl*2 + 1]);
            float* orow = attnout + ((size_t)bt * NN + n) * 128;
#pragma unroll
            for (int nt = 0; nt < 8; nt++)
#pragma unroll
                for (int j = 0; j < 2; j++) {
                    int f = wn*64 + nt*8 + rg*2 + j;
                    orow[f] = rnd_tf32(Oacc[mt][nt][i2*2 + j] * inv);
                }
        }
}

// ---------------- conv as K=975 GEMM, fused gate: grid (3, BT) ----------
__global__ __launch_bounds__(256)
void conv_tc(const float* __restrict__ cw /*[325][992]*/,
             const float* __restrict__ vn, const float* __restrict__ cb,
             const float* __restrict__ gres, const float* __restrict__ hbuf,
             float* __restrict__ sg)
{
    extern __shared__ float sm[];
    float* As = sm;                 // [2][128][36]  (cw rows: [n][k])
    float* Bs = sm + 2*128*36;      // [2][32][136]  (vn shifted rows: [k][f])
    const int bt = blockIdx.y, n0 = blockIdx.x * 128;
    const int tid = threadIdx.x;
    const float* vbt = vn + (size_t)bt * NN * 128;
    const int NKT = 31;   // ceil(975/32)

#define LOAD_T(stage, k0) do {                                               \
        float* Ad = As + (stage)*128*36;                                     \
        float* Bd = Bs + (stage)*32*136;                                     \
        _Pragma("unroll")                                                    \
        for (int i = 0; i < 4; i++) {                                        \
            int lin = tid + 256*i;                                           \
            int r = lin >> 3, ch = lin & 7;                                  \
            bool p = (n0 + r) < NN;                                          \
            cp16(sptr(Ad + r*36 + ch*4),                                     \
                 cw + (size_t)(n0 + r)*992 + (k0) + ch*4, p);                \
        }                                                                    \
        _Pragma("unroll")                                                    \
        for (int i = 0; i < 16; i++) {                                       \
            int lin = tid + 256*i;                                           \
            int kr = lin >> 7, f = lin & 127;                                \
            int kg = (k0) + kr;                                              \
            int m = kg / 3, tap = kg - m*3;                                  \
            int fs = f + tap - 1;                                            \
            bool p = (kg < 975) && (fs >= 0) && (fs < 128);                  \
            const float* src = p ? (vbt + (size_t)m*128 + fs) : vbt;         \
            cp4(sptr(Bd + kr*136 + f), src, p);                              \
        }                                                                    \
        CP_COMMIT();                                                         \
    } while (0)

    LOAD_T(0, 0);
    LOAD_T(1, 32);
    CP_WAIT(1);
    __syncthreads();

    const int lane = tid & 31, wid = tid >> 5;
    const int wm = wid >> 1, wn = wid & 1;
    const int qg = lane >> 2, rg = lane & 3;
    float acc[2][8][4];
#pragma unroll
    for (int a = 0; a < 2; a++)
#pragma unroll
        for (int b = 0; b < 8; b++)
#pragma unroll
            for (int c = 0; c < 4; c++) acc[a][b][c] = 0.f;

    for (int kt = 0; kt < NKT; kt++) {
        const float* Ac = As + (kt & 1) * 128 * 36;
        const float* Bc = Bs + (kt & 1) * 32 * 136;
#pragma unroll
        for (int ks = 0; ks < 4; ks++) {
            int kk = ks * 8;
            float af[2][4], bf[8][2];
#pragma unroll
            for (int mt = 0; mt < 2; mt++) {
                int r = wm*32 + mt*16 + qg;
                af[mt][0] = Ac[(r)    *36 + kk + rg];
                af[mt][1] = Ac[(r + 8)*36 + kk + rg];
                af[mt][2] = Ac[(r)    *36 + kk + rg + 4];
                af[mt][3] = Ac[(r + 8)*36 + kk + rg + 4];
            }
#pragma unroll
            for (int nt = 0; nt < 8; nt++) {
                int c = wn*64 + nt*8 + qg;
                bf[nt][0] = Bc[(kk + rg)    *136 + c];
                bf[nt][1] = Bc[(kk + rg + 4)*136 + c];
            }
#pragma unroll
            for (int mt = 0; mt < 2; mt++)
#pragma unroll
                for (int nt = 0; nt < 8; nt++)
                    mma_tf32(acc[mt][nt][0], acc[mt][nt][1], acc[mt][nt][2], acc[mt][nt][3],
                             af[mt][0], af[mt][1], af[mt][2], af[mt][3],
                             bf[nt][0], bf[nt][1]);
        }
        if (kt + 2 < NKT) {
            __syncthreads();
            LOAD_T(kt & 1, (kt + 2) * 32);
            CP_WAIT(1);
            __syncthreads();
        } else if (kt + 1 < NKT) {
            CP_WAIT(0);
            __syncthreads();
        }
    }
#undef LOAD_T
    // epilogue: sg = (acc + cb[n] + gres) * u, rounded
#pragma unroll
    for (int mt = 0; mt < 2; mt++)
#pragma unroll
        for (int i2 = 0; i2 < 2; i2++) {
            int n = n0 + wm*32 + mt*16 + qg + i2*8;
            if (n >= NN) continue;
            size_t row = (size_t)bt * NN + n;
            float bias = cb[n];
#pragma unroll
            for (int nt = 0; nt < 8; nt++)
#pragma unroll
                for (int j = 0; j < 2; j++) {
                    int f = wn*64 + nt*8 + rg*2 + j;
                    float v = acc[mt][nt][i2*2 + j] + bias + gres[row*128 + f];
                    sg[row*128 + f] = rnd_tf32(v * hbuf[row*256 + f]);
                }
        }
}

// ---------------- host launcher ----------------
extern "C" void kernel_launch(void* const* d_in, const int* in_sizes, int n_in,
                              void* d_out, int out_size)
{
    const float* x      = (const float*)d_in[0];
    const float* norm_g = (const float*)d_in[1];
    const float* norm_b = (const float*)d_in[2];
    const float* W1     = (const float*)d_in[3];
    const float* b1     = (const float*)d_in[4];
    const float* aff1_W = (const float*)d_in[5];
    const float* aff1_b = (const float*)d_in[6];
    const float* Wl     = (const float*)d_in[7];
    const float* bl     = (const float*)d_in[8];
    const float* sgu_g  = (const float*)d_in[9];
    const float* sgu_b  = (const float*)d_in[10];
    const float* conv_w = (const float*)d_in[11];
    const float* conv_b = (const float*)d_in[12];
    const float* Wqkv   = (const float*)d_in[13];
    const float* bqkv   = (const float*)d_in[14];
    const float* Wo     = (const float*)d_in[15];
    const float* bo     = (const float*)d_in[16];
    const float* W2     = (const float*)d_in[17];
    const float* b2     = (const float*)d_in[18];
    float* out = (float*)d_out;

    float *xn, *qkv, *coords, *h, *attnout, *gateres, *vn, *sg;
    float *wqkv, *w1, *wo, *w2, *cw;
    cudaGetSymbolAddress((void**)&xn,      g_xn);
    cudaGetSymbolAddress((void**)&qkv,     g_qkv);
    cudaGetSymbolAddress((void**)&coords,  g_coords);
    cudaGetSymbolAddress((void**)&h,       g_h);
    cudaGetSymbolAddress((void**)&attnout, g_attnout);
    cudaGetSymbolAddress((void**)&gateres, g_gateres);
    cudaGetSymbolAddress((void**)&vn,      g_vn);
    cudaGetSymbolAddress((void**)&sg,      g_sg);
    cudaGetSymbolAddress((void**)&wqkv,    g_wqkv);
    cudaGetSymbolAddress((void**)&w1,      g_w1);
    cudaGetSymbolAddress((void**)&wo,      g_wo);
    cudaGetSymbolAddress((void**)&w2,      g_w2);
    cudaGetSymbolAddress((void**)&cw,      g_cw);

    const int GEMM_SMEM = (128*136 + 2*128*36) * 4;           // 106496
    const int CONV_SMEM = (2*128*36 + 2*32*136) * 4;          // 71680
    const int ATTN_SMEM = (2*128*132 + 128*136 + 256) * 4;    // 205824
    static bool attr_done = false;
    if (!attr_done) {
        cudaFuncSetAttribute(gemm128<0, true>,  cudaFuncAttributeMaxDynamicSharedMemorySize, GEMM_SMEM);
        cudaFuncSetAttribute(gemm128<1, false>, cudaFuncAttributeMaxDynamicSharedMemorySize, GEMM_SMEM);
        cudaFuncSetAttribute(gemm128<0, false>, cudaFuncAttributeMaxDynamicSharedMemorySize, GEMM_SMEM);
        cudaFuncSetAttribute(gemm128<2, false>, cudaFuncAttributeMaxDynamicSharedMemorySize, GEMM_SMEM);
        cudaFuncSetAttribute(conv_tc,           cudaFuncAttributeMaxDynamicSharedMemorySize, CONV_SMEM);
        cudaFuncSetAttribute(attn_kernel,       cudaFuncAttributeMaxDynamicSharedMemorySize, ATTN_SMEM);
        attr_done = true;
    }

    const int rowBlocks = (MT + 7) / 8;

    // 0) round weights into scratch
    prep_kernel<<<(437088 + 255) / 256, 256>>>(Wqkv, W1, Wo, W2, conv_w,
                                               wqkv, w1, wo, w2, cw);
    // 1) LN(x) -> xn (rounded) + coords
    ln_kernel<<<rowBlocks, 256>>>(x, 128, xn, norm_g, norm_b, MT, coords, Wl, bl);
    // 2) qkv = xn @ Wqkv + bqkv (rounded output)
    {
        dim3 g(3, 975);
        gemm128<0, true><<<g, 256, GEMM_SMEM>>>(xn, wqkv, 384, qkv, 384, 384,
                                                bqkv, nullptr, nullptr, nullptr);
    }
    // 3) h = relu(xn @ W1 + b1 + coords-affine)
    {
        dim3 g(2, 975);
        gemm128<1, false><<<g, 256, GEMM_SMEM>>>(xn, w1, 256, h, 256, 256,
                                                 b1, coords, aff1_W, aff1_b);
    }
    // 4) fused attention -> attnout (rounded)
    {
        dim3 g(3, BT);
        attn_kernel<<<g, 256, ATTN_SMEM>>>(qkv, attnout);
    }
    // 5) gate_res = attnout @ Wo + bo
    {
        dim3 g(1, 975);
        gemm128<0, false><<<g, 256, GEMM_SMEM>>>(attnout, wo, 128, gateres, 128, 128,
                                                 bo, nullptr, nullptr, nullptr);
    }
    // 6) vn = LN(h[:,128:256]) (rounded)
    ln_kernel<<<rowBlocks, 256>>>(h + 128, 256, vn, sgu_g, sgu_b, MT,
                                  nullptr, nullptr, nullptr);
    // 7) conv GEMM + gate -> sg (rounded)
    {
        dim3 g(3, BT);
        conv_tc<<<g, 256, CONV_SMEM>>>(cw, vn, conv_b, gateres, h, sg);
    }
    // 8) out = relu(sg @ W2 + b2) + x
    {
        dim3 g(1, 975);
        gemm128<2, false><<<g, 256, GEMM_SMEM>>>(sg, w2, 128, out, 128, 128,
                                                 b2, x, nullptr, nullptr);
    }
}